// round 16
// baseline (speedup 1.0000x reference)
#include <cuda_runtime.h>

#define FULLMASK 0xffffffffu

constexpr int NMAX = 50000;
constexpr int EMAX = 850000;   // 800000 edges + 50000 self loops
constexpr int HDIM = 32;
constexpr int TS = 36;         // tile row stride in floats (144B)

// ---------------- scratch (device globals; no allocation) ----------------
// Invariant: g_deg all-zero on entry (zero-init at load, re-zeroed by k_scan23).
__device__ float g_h[NMAX * HDIM];    // relu'd layer output (k_edge -> k_gemm)
__device__ float g_hp[NMAX * HDIM];   // W-transformed features (k_gemm -> k_edge)
__device__ float g_pl[NMAX];
__device__ float g_pr[NMAX];
__device__ int   g_deg[NMAX];
__device__ int   g_rowptr[NMAX + 1];
__device__ int   g_cursor[NMAX];
__device__ int   g_col[EMAX];
__device__ int   g_bsum[512];

// ---------------- cp.async helpers ----------------
__device__ __forceinline__ void cp16(unsigned dst, const void* src) {
    asm volatile("cp.async.cg.shared.global [%0], [%1], 16;\n" :: "r"(dst), "l"(src));
}
__device__ __forceinline__ void cp_commit() {
    asm volatile("cp.async.commit_group;\n" ::: "memory");
}
__device__ __forceinline__ void cp_wait0() {
    asm volatile("cp.async.wait_group 0;\n" ::: "memory");
}

// ---------------- packed f32x2 helpers (sm_103a FFMA2) ----------------
__device__ __forceinline__ void fma2(unsigned long long& d, unsigned long long a,
                                     unsigned long long b) {
    asm("fma.rn.f32x2 %0, %1, %2, %0;" : "+l"(d) : "l"(a), "l"(b));
}
__device__ __forceinline__ unsigned long long pack2(float x) {
    unsigned long long r;
    asm("mov.b64 %0, {%1, %1};" : "=l"(r) : "r"(__float_as_uint(x)));
    return r;
}
__device__ __forceinline__ float2 unpack2(unsigned long long v) {
    unsigned lo, hi;
    asm("mov.b64 {%0, %1}, %2;" : "=r"(lo), "=r"(hi) : "l"(v));
    return make_float2(__uint_as_float(lo), __uint_as_float(hi));
}

// ---------------- fast math (no MUFU) ----------------
__device__ __forceinline__ float fexp(float x) {
    x = fmaxf(x, -87.0f);
    float t = x * 1.4426950408889634f;
    float r2 = t + 12582912.0f;
    int   n  = __float_as_int(r2) - 0x4B400000;
    float f  = t - (r2 - 12582912.0f);
    float p  = 1.5398530e-4f;
    p = fmaf(p, f, 1.3333558e-3f);
    p = fmaf(p, f, 9.6181291e-3f);
    p = fmaf(p, f, 5.5504109e-2f);
    p = fmaf(p, f, 2.4022651e-1f);
    p = fmaf(p, f, 6.9314718e-1f);
    p = fmaf(p, f, 1.0f);
    float s = __int_as_float((n + 127) << 23);
    return p * s;
}

__device__ __forceinline__ float rcp1p(float e) {
    float d = 1.0f + e;
    float y = fmaf(d, -0.47058824f, 1.41176471f);
    y = y * fmaf(-d, y, 2.0f);
    y = y * fmaf(-d, y, 2.0f);
    return y;
}

__device__ __forceinline__ void fma4(float4& a, float s, const float4& b) {
    a.x = fmaf(s, b.x, a.x);
    a.y = fmaf(s, b.y, a.y);
    a.z = fmaf(s, b.z, a.z);
    a.w = fmaf(s, b.w, a.w);
}

// ---------------- CSR build (R13 structure) ----------------
__global__ void k_count(const int* __restrict__ ei, int E) {
    int e = blockIdx.x * blockDim.x + threadIdx.x;
    if (e < E) atomicAdd(&g_deg[ei[E + e]], 1);
}

__global__ void k_scan1(int N) {
    __shared__ int sm[512];
    int i = blockIdx.x * 512 + threadIdx.x;
    int v = (i < N) ? (g_deg[i] + 1) : 0;       // +1 self loop
    sm[threadIdx.x] = v;
    __syncthreads();
    #pragma unroll
    for (int off = 1; off < 512; off <<= 1) {
        int t = (threadIdx.x >= off) ? sm[threadIdx.x - off] : 0;
        __syncthreads();
        sm[threadIdx.x] += t;
        __syncthreads();
    }
    if (i < N) g_cursor[i] = sm[threadIdx.x];
    if (threadIdx.x == 511) g_bsum[blockIdx.x] = sm[511];
}

__global__ void k_scan23(int N, int nb) {
    __shared__ int pre;
    if (threadIdx.x == 0) {
        int run = 0;
        for (int b = 0; b < (int)blockIdx.x; b++) run += g_bsum[b];
        pre = run;
    }
    __syncthreads();
    int i = blockIdx.x * 512 + threadIdx.x;
    if (i < N) {
        int incl = g_cursor[i] + pre;
        int deg  = g_deg[i] + 1;
        int excl = incl - deg;
        g_rowptr[i] = excl;
        g_cursor[i] = excl;
        g_deg[i] = 0;
        if (i == N - 1) g_rowptr[N] = incl;
    }
}

__global__ void k_scatter(const int* __restrict__ ei, int E, int N) {
    int e = blockIdx.x * blockDim.x + threadIdx.x;
    if (e >= E + N) return;
    int s, d;
    if (e < E) { s = ei[e]; d = ei[E + e]; }
    else       { s = e - E; d = s; }
    int pos = atomicAdd(&g_cursor[d], 1);
    g_col[pos] = s;
}

__global__ void k_sort(int N) {
    int warp = (blockIdx.x * blockDim.x + threadIdx.x) >> 5;
    int lane = threadIdx.x & 31;
    if (warp >= N) return;
    int beg = g_rowptr[warp];
    int cnt = g_rowptr[warp + 1] - beg;
    if (cnt <= 1) return;
    if (cnt <= 32) {
        int v = (lane < cnt) ? g_col[beg + lane] : 0x7fffffff;
        #pragma unroll
        for (int k = 2; k <= 32; k <<= 1) {
            #pragma unroll
            for (int jj = k >> 1; jj > 0; jj >>= 1) {
                int p = __shfl_xor_sync(FULLMASK, v, jj);
                bool up = ((lane & k) == 0);
                bool keepmin = (((lane & jj) == 0) == up);
                v = keepmin ? min(v, p) : max(v, p);
            }
        }
        if (lane < cnt) g_col[beg + lane] = v;
    } else if (lane == 0) {
        for (int a = 1; a < cnt; a++) {
            int key = g_col[beg + a], b = a - 1;
            while (b >= 0 && g_col[beg + b] > key) { g_col[beg + b + 1] = g_col[beg + b]; b--; }
            g_col[beg + b + 1] = key;
        }
    }
}

// ---------------- per-layer GEMM: coalesced smem staging + packed FFMA2 ----------------
__global__ void __launch_bounds__(128) k_gemm(
    const float* __restrict__ Wl, const float* __restrict__ al, const float* __restrict__ ar,
    int N)
{
    __shared__ float4 W4[HDIM * 8];
    __shared__ float4 al4[8], ar4[8];
    __shared__ float hbuf[128 * TS];          // 18 KB staging (rows padded to 36)
    int tid = threadIdx.x;
    for (int q = tid; q < HDIM * 8; q += 128) W4[q] = reinterpret_cast<const float4*>(Wl)[q];
    if (tid < 8) { al4[tid] = reinterpret_cast<const float4*>(al)[tid];
                   ar4[tid] = reinterpret_cast<const float4*>(ar)[tid]; }

    int nb = blockIdx.x * 128;
    int vrows = min(128, N - nb);
    int limit4 = vrows * 8;

    const float4* src = reinterpret_cast<const float4*>(g_h + (size_t)nb * HDIM);
    #pragma unroll
    for (int u = 0; u < 8; u++) {
        int q = tid + u * 128;
        if (q < limit4)
            *reinterpret_cast<float4*>(hbuf + (q >> 3) * TS + (q & 7) * 4) = src[q];
    }
    __syncthreads();

    int n = nb + tid;
    bool valid = n < N;
    unsigned long long acc2[16];
    if (valid) {
        float hs[32];
        #pragma unroll
        for (int u = 0; u < 8; u++) {
            float4 v = *reinterpret_cast<const float4*>(hbuf + tid * TS + 4 * u);
            hs[4*u] = v.x; hs[4*u+1] = v.y; hs[4*u+2] = v.z; hs[4*u+3] = v.w;
        }
        #pragma unroll
        for (int m = 0; m < 16; m++) acc2[m] = 0ull;
        #pragma unroll
        for (int k = 0; k < 32; k++) {
            unsigned long long ok2 = pack2(hs[k]);
            const ulonglong2* wp = reinterpret_cast<const ulonglong2*>(&W4[k * 8]);
            #pragma unroll
            for (int m = 0; m < 8; m++) {
                ulonglong2 w2 = wp[m];
                fma2(acc2[2*m],     ok2, w2.x);
                fma2(acc2[2*m + 1], ok2, w2.y);
            }
        }
    }
    __syncthreads();

    if (valid) {
        #pragma unroll
        for (int m = 0; m < 16; m++) {
            float2 f = unpack2(acc2[m]);
            hbuf[tid * TS + 2*m]     = f.x;
            hbuf[tid * TS + 2*m + 1] = f.y;
        }
    }
    __syncthreads();

    float4* dst = reinterpret_cast<float4*>(g_hp + (size_t)nb * HDIM);
    #pragma unroll
    for (int u = 0; u < 8; u++) {
        int q = tid + u * 128;
        if (q < limit4)
            dst[q] = *reinterpret_cast<const float4*>(hbuf + (q >> 3) * TS + (q & 7) * 4);
    }

    if (valid) {
        float t1 = 0.f, t2 = 0.f;
        #pragma unroll
        for (int j = 0; j < 8; j++) {
            float4 c = *reinterpret_cast<const float4*>(hbuf + tid * TS + 4 * j);
            float4 a4 = al4[j], r4 = ar4[j];
            t1 = fmaf(c.x, a4.x, t1); t1 = fmaf(c.y, a4.y, t1);
            t1 = fmaf(c.z, a4.z, t1); t1 = fmaf(c.w, a4.w, t1);
            t2 = fmaf(c.x, r4.x, t2); t2 = fmaf(c.y, r4.y, t2);
            t2 = fmaf(c.z, r4.z, t2); t2 = fmaf(c.w, r4.w, t2);
        }
        g_pl[n] = t1; g_pr[n] = t2;
    }
}

__global__ void __launch_bounds__(128) k_gemm_first(
    const float* __restrict__ x, const float* __restrict__ W0, const float* __restrict__ b0,
    const float* __restrict__ Ws0, const float* __restrict__ al, const float* __restrict__ ar,
    int N)
{
    __shared__ float4 W04[128 * 8];
    __shared__ float4 W4[HDIM * 8];
    __shared__ float4 b04[8], al4[8], ar4[8];
    int tid = threadIdx.x;
    for (int q = tid; q < 128 * 8; q += 128) W04[q] = reinterpret_cast<const float4*>(W0)[q];
    for (int q = tid; q < HDIM * 8; q += 128) W4[q] = reinterpret_cast<const float4*>(Ws0)[q];
    if (tid < 8) { b04[tid] = reinterpret_cast<const float4*>(b0)[tid];
                   al4[tid] = reinterpret_cast<const float4*>(al)[tid];
                   ar4[tid] = reinterpret_cast<const float4*>(ar)[tid]; }
    __syncthreads();

    int n = blockIdx.x * 128 + tid;
    if (n >= N) return;

    float4 h4[8];
    #pragma unroll
    for (int j = 0; j < 8; j++) h4[j] = b04[j];
    #pragma unroll 4
    for (int k4 = 0; k4 < 32; k4++) {
        float4 xv = reinterpret_cast<const float4*>(x + n * 128)[k4];
        #pragma unroll
        for (int j = 0; j < 8; j++) {
            fma4(h4[j], xv.x, W04[(4*k4+0) * 8 + j]);
            fma4(h4[j], xv.y, W04[(4*k4+1) * 8 + j]);
            fma4(h4[j], xv.z, W04[(4*k4+2) * 8 + j]);
            fma4(h4[j], xv.w, W04[(4*k4+3) * 8 + j]);
        }
    }
    float hs[32];
    #pragma unroll
    for (int u = 0; u < 8; u++) {
        hs[4*u] = h4[u].x; hs[4*u+1] = h4[u].y; hs[4*u+2] = h4[u].z; hs[4*u+3] = h4[u].w;
    }
    float4 acc[8];
    #pragma unroll
    for (int j = 0; j < 8; j++) acc[j] = make_float4(0.f, 0.f, 0.f, 0.f);
    #pragma unroll
    for (int k = 0; k < 32; k++) {
        float ok = hs[k];
        #pragma unroll
        for (int j = 0; j < 8; j++) fma4(acc[j], ok, W4[k * 8 + j]);
    }
    float t1 = 0.f, t2 = 0.f;
    #pragma unroll
    for (int j = 0; j < 8; j++) {
        float4 a4 = al4[j], r4 = ar4[j], c = acc[j];
        t1 = fmaf(c.x, a4.x, t1); t1 = fmaf(c.y, a4.y, t1);
        t1 = fmaf(c.z, a4.z, t1); t1 = fmaf(c.w, a4.w, t1);
        t2 = fmaf(c.x, r4.x, t2); t2 = fmaf(c.y, r4.y, t2);
        t2 = fmaf(c.z, r4.z, t2); t2 = fmaf(c.w, r4.w, t2);
        reinterpret_cast<float4*>(g_hp + n * HDIM)[j] = c;
    }
    g_pl[n] = t1; g_pr[n] = t2;
}

__global__ void __launch_bounds__(128) k_gemm_last(
    const float* __restrict__ W16, const float* __restrict__ b16,
    float* __restrict__ out, int N)
{
    __shared__ float4 W4[HDIM * 4];
    __shared__ float4 b4[4];
    int tid = threadIdx.x;
    for (int q = tid; q < HDIM * 4; q += 128) W4[q] = reinterpret_cast<const float4*>(W16)[q];
    if (tid < 4) b4[tid] = reinterpret_cast<const float4*>(b16)[tid];
    __syncthreads();

    int n = blockIdx.x * 128 + tid;
    if (n >= N) return;

    float hs[32];
    #pragma unroll
    for (int u = 0; u < 8; u++) {
        float4 v = reinterpret_cast<const float4*>(g_h + n * HDIM)[u];
        hs[4*u] = v.x; hs[4*u+1] = v.y; hs[4*u+2] = v.z; hs[4*u+3] = v.w;
    }
    float4 acc[4];
    #pragma unroll
    for (int j = 0; j < 4; j++) acc[j] = b4[j];
    #pragma unroll
    for (int k = 0; k < 32; k++) {
        float ok = hs[k];
        #pragma unroll
        for (int j = 0; j < 4; j++) fma4(acc[j], ok, W4[k * 4 + j]);
    }
    #pragma unroll
    for (int j = 0; j < 4; j++) reinterpret_cast<float4*>(out + n * 16)[j] = acc[j];
}

// ---------------- edge layer (R13 + butterfly dot reduce) ----------------
// Warp = 4 groups x 8 lanes. Lane (g,j): float4 slice j, softmax edge perm=4j+g.
// Dot pass: XOR-butterfly — lane (g,j) computes 8 partials p[k] for edge
// 4(k^j)+g from its slice, then 7 shfl_xor reduce all 8 group dots at once
// (same per-edge summation tree as before -> bitwise-identical dotv).
// Invalid edges may read stale rows (NaN possible); wv's select zeroes them.
__global__ void __launch_bounds__(256) k_edge(
    const float* __restrict__ bcur, int N)
{
    __shared__ float tile[8][32 * TS];      // 36864 B
    __shared__ float bsm[HDIM];

    int tid = threadIdx.x;
    if (tid < HDIM) bsm[tid] = bcur[tid];
    __syncthreads();

    const float* __restrict__ hp_in = g_hp;
    const float* __restrict__ pl_in = g_pl;
    const float* __restrict__ pr_in = g_pr;

    int lane = tid & 31;
    int g = lane >> 3;
    int j = lane & 7;
    int perm = 4 * j + g;
    int gb = lane & 24;

    int w = tid >> 5;
    float* tw = tile[w];
    unsigned tb = (unsigned)__cvta_generic_to_shared(tw) + (unsigned)(g * TS * 4 + j * 16);
    const char* hpb = reinterpret_cast<const char*>(hp_in);

    int wg = (blockIdx.x * blockDim.x + tid) >> 5;
    int nw = (gridDim.x * blockDim.x) >> 5;

    for (int i = wg; i < N; i += nw) {
        float4 hi4 = *reinterpret_cast<const float4*>(hp_in + i * HDIM + 4 * j);
        float pri = pr_in[i];
        int beg = g_rowptr[i], end = g_rowptr[i + 1];

        float den = 0.0f;
        float4 acc = make_float4(0.f, 0.f, 0.f, 0.f);

        for (int c = beg; c < end; c += 32) {
            int cnt = min(32, end - c);
            bool vld = perm < cnt;
            int s = g_col[c + min(perm, cnt - 1)];
            float pls = vld ? pl_in[s] : 0.0f;

            __syncwarp();
            #pragma unroll
            for (int t = 0; t < 8; t++) {
                if (4 * t < cnt) {
                    int se = __shfl_sync(FULLMASK, s, gb + t);
                    cp16(tb + (unsigned)(t * (4 * TS * 4)),
                         hpb + ((long long)se * 128 + j * 16));
                }
            }
            cp_commit();
            cp_wait0();
            __syncwarp();

            // ---- butterfly dot: 8 unconditional partials + 7 shfl ----
            float p0, p1, p2, p3, p4, p5, p6, p7;
            {
                const float* twj = tw + 4 * j;
                float4 h;
                h = *reinterpret_cast<const float4*>(twj + (4 * (0 ^ j) + g) * TS);
                p0 = h.x*hi4.x; p0 = fmaf(h.y,hi4.y,p0); p0 = fmaf(h.z,hi4.z,p0); p0 = fmaf(h.w,hi4.w,p0);
                h = *reinterpret_cast<const float4*>(twj + (4 * (1 ^ j) + g) * TS);
                p1 = h.x*hi4.x; p1 = fmaf(h.y,hi4.y,p1); p1 = fmaf(h.z,hi4.z,p1); p1 = fmaf(h.w,hi4.w,p1);
                h = *reinterpret_cast<const float4*>(twj + (4 * (2 ^ j) + g) * TS);
                p2 = h.x*hi4.x; p2 = fmaf(h.y,hi4.y,p2); p2 = fmaf(h.z,hi4.z,p2); p2 = fmaf(h.w,hi4.w,p2);
                h = *reinterpret_cast<const float4*>(twj + (4 * (3 ^ j) + g) * TS);
                p3 = h.x*hi4.x; p3 = fmaf(h.y,hi4.y,p3); p3 = fmaf(h.z,hi4.z,p3); p3 = fmaf(h.w,hi4.w,p3);
                h = *reinterpret_cast<const float4*>(twj + (4 * (4 ^ j) + g) * TS);
                p4 = h.x*hi4.x; p4 = fmaf(h.y,hi4.y,p4); p4 = fmaf(h.z,hi4.z,p4); p4 = fmaf(h.w,hi4.w,p4);
                h = *reinterpret_cast<const float4*>(twj + (4 * (5 ^ j) + g) * TS);
                p5 = h.x*hi4.x; p5 = fmaf(h.y,hi4.y,p5); p5 = fmaf(h.z,hi4.z,p5); p5 = fmaf(h.w,hi4.w,p5);
                h = *reinterpret_cast<const float4*>(twj + (4 * (6 ^ j) + g) * TS);
                p6 = h.x*hi4.x; p6 = fmaf(h.y,hi4.y,p6); p6 = fmaf(h.z,hi4.z,p6); p6 = fmaf(h.w,hi4.w,p6);
                h = *reinterpret_cast<const float4*>(twj + (4 * (7 ^ j) + g) * TS);
                p7 = h.x*hi4.x; p7 = fmaf(h.y,hi4.y,p7); p7 = fmaf(h.z,hi4.z,p7); p7 = fmaf(h.w,hi4.w,p7);
            }
            p0 += __shfl_xor_sync(FULLMASK, p4, 4);
            p1 += __shfl_xor_sync(FULLMASK, p5, 4);
            p2 += __shfl_xor_sync(FULLMASK, p6, 4);
            p3 += __shfl_xor_sync(FULLMASK, p7, 4);
            p0 += __shfl_xor_sync(FULLMASK, p2, 2);
            p1 += __shfl_xor_sync(FULLMASK, p3, 2);
            float dotv = p0 + __shfl_xor_sync(FULLMASK, p1, 1);   // edge 4j+g

            float e1  = fexp(-fabsf(dotv));
            float r   = rcp1p(e1);
            float sig = (dotv >= 0.0f) ? r : 1.0f - r;
            float a   = (pls + pri) * sig;
            a = (a >= 0.0f) ? a : 0.2f * a;
            a = fminf(a, 80.0f);                       // overflow guard

            float wv = vld ? fexp(a) : 0.0f;           // exact 0 for padding/NaN lanes
            float ws = wv;
            #pragma unroll
            for (int off = 16; off; off >>= 1) ws += __shfl_xor_sync(FULLMASK, ws, off);
            den += ws;

            #pragma unroll
            for (int t = 0; t < 8; t++) {
                if (4 * t < cnt) {
                    float we = __shfl_sync(FULLMASK, wv, gb + t);
                    const float4 hj = *reinterpret_cast<const float4*>(tw + (4 * t + g) * TS + 4 * j);
                    acc.x = fmaf(we, hj.x, acc.x);
                    acc.y = fmaf(we, hj.y, acc.y);
                    acc.z = fmaf(we, hj.z, acc.z);
                    acc.w = fmaf(we, hj.w, acc.w);
                }
            }
        }

        #pragma unroll
        for (int off = 8; off <= 16; off <<= 1) {
            acc.x += __shfl_xor_sync(FULLMASK, acc.x, off);
            acc.y += __shfl_xor_sync(FULLMASK, acc.y, off);
            acc.z += __shfl_xor_sync(FULLMASK, acc.z, off);
            acc.w += __shfl_xor_sync(FULLMASK, acc.w, off);
        }
        if (g == 0) {
            float rden = __fdividef(1.0f, den);
            float4 b4 = *reinterpret_cast<const float4*>(bsm + 4 * j);
            float4 o4;
            o4.x = fmaxf(fmaf(acc.x, rden, b4.x), 0.0f);
            o4.y = fmaxf(fmaf(acc.y, rden, b4.y), 0.0f);
            o4.z = fmaxf(fmaf(acc.z, rden, b4.z), 0.0f);
            o4.w = fmaxf(fmaf(acc.w, rden, b4.w), 0.0f);
            *reinterpret_cast<float4*>(g_h + i * HDIM + 4 * j) = o4;
        }
    }
}

// ---------------- host (R13 structure verbatim) ----------------
extern "C" void kernel_launch(void* const* d_in, const int* in_sizes, int n_in,
                              void* d_out, int out_size) {
    const float* x   = (const float*)d_in[0];
    const int*   ei  = (const int*)d_in[1];
    const float* W0  = (const float*)d_in[2];
    const float* b0  = (const float*)d_in[3];
    const float* Ws  = (const float*)d_in[4];
    const float* al  = (const float*)d_in[5];
    const float* ar  = (const float*)d_in[6];
    const float* bs  = (const float*)d_in[7];
    const float* W16 = (const float*)d_in[8];
    const float* b16 = (const float*)d_in[9];
    float* out = (float*)d_out;

    const int N = in_sizes[0] / 128;
    const int E = in_sizes[1] / 2;
    const int L = 15;
    const int nb = (N + 511) / 512;
    const int gN = (N + 127) / 128;

    // ---- CSR build (R13 layout) ----
    k_count <<<(E + 255) / 256, 256>>>(ei, E);
    k_scan1 <<<nb, 512>>>(N);
    k_scan23<<<nb, 512>>>(N, nb);
    k_scatter<<<(E + N + 255) / 256, 256>>>(ei, E, N);
    k_sort  <<<(N * 32 + 255) / 256, 256>>>(N);

    // ---- input transform ----
    k_gemm_first<<<gN, 128>>>(x, W0, b0, Ws, al, ar, N);

    // ---- 15 SuperGAT layers ----
    for (int l = 0; l < L; l++) {
        k_edge<<<740, 256>>>(bs + l * 32, N);
        if (l < L - 1)
            k_gemm<<<gN, 128>>>(Ws + (l + 1) * 32 * 32, al + (l + 1) * 32, ar + (l + 1) * 32, N);
        else
            k_gemm_last<<<gN, 128>>>(W16, b16, out, N);
    }
}

// round 17
// speedup vs baseline: 1.2968x; 1.2968x over previous
#include <cuda_runtime.h>

#define FULLMASK 0xffffffffu

constexpr int NMAX = 50000;
constexpr int EMAX = 850000;   // 800000 edges + 50000 self loops
constexpr int HDIM = 32;
constexpr int TS = 36;         // tile row stride in floats (144B)

// ---------------- scratch (device globals; no allocation) ----------------
// Invariant: g_deg all-zero on entry (zero-init at load, re-zeroed by k_scan23).
__device__ float g_h[NMAX * HDIM];    // relu'd layer output (k_edge -> k_gemm)
__device__ float g_hp[NMAX * HDIM];   // W-transformed features (k_gemm -> k_edge)
__device__ float g_pl[NMAX];
__device__ float g_pr[NMAX];
__device__ int   g_deg[NMAX];
__device__ int   g_rowptr[NMAX + 1];
__device__ int   g_cursor[NMAX];
__device__ int   g_col[EMAX];
__device__ int   g_bsum[512];

// ---------------- PDL: wait for producer grid before reading its output ----------------
__device__ __forceinline__ void gdc_wait() {
    asm volatile("griddepcontrol.wait;" ::: "memory");
}

// ---------------- cp.async helpers ----------------
__device__ __forceinline__ void cp16(unsigned dst, const void* src) {
    asm volatile("cp.async.cg.shared.global [%0], [%1], 16;\n" :: "r"(dst), "l"(src));
}
__device__ __forceinline__ void cp_commit() {
    asm volatile("cp.async.commit_group;\n" ::: "memory");
}
__device__ __forceinline__ void cp_wait0() {
    asm volatile("cp.async.wait_group 0;\n" ::: "memory");
}

// ---------------- packed f32x2 helpers (sm_103a FFMA2) ----------------
__device__ __forceinline__ void fma2(unsigned long long& d, unsigned long long a,
                                     unsigned long long b) {
    asm("fma.rn.f32x2 %0, %1, %2, %0;" : "+l"(d) : "l"(a), "l"(b));
}
__device__ __forceinline__ unsigned long long pack2(float x) {
    unsigned long long r;
    asm("mov.b64 %0, {%1, %1};" : "=l"(r) : "r"(__float_as_uint(x)));
    return r;
}
__device__ __forceinline__ float2 unpack2(unsigned long long v) {
    unsigned lo, hi;
    asm("mov.b64 {%0, %1}, %2;" : "=r"(lo), "=r"(hi) : "l"(v));
    return make_float2(__uint_as_float(lo), __uint_as_float(hi));
}

// ---------------- fast math (no MUFU) ----------------
__device__ __forceinline__ float fexp(float x) {
    x = fmaxf(x, -87.0f);
    float t = x * 1.4426950408889634f;
    float r2 = t + 12582912.0f;
    int   n  = __float_as_int(r2) - 0x4B400000;
    float f  = t - (r2 - 12582912.0f);
    float p  = 1.5398530e-4f;
    p = fmaf(p, f, 1.3333558e-3f);
    p = fmaf(p, f, 9.6181291e-3f);
    p = fmaf(p, f, 5.5504109e-2f);
    p = fmaf(p, f, 2.4022651e-1f);
    p = fmaf(p, f, 6.9314718e-1f);
    p = fmaf(p, f, 1.0f);
    float s = __int_as_float((n + 127) << 23);
    return p * s;
}

__device__ __forceinline__ float rcp1p(float e) {
    float d = 1.0f + e;
    float y = fmaf(d, -0.47058824f, 1.41176471f);
    y = y * fmaf(-d, y, 2.0f);
    y = y * fmaf(-d, y, 2.0f);
    return y;
}

__device__ __forceinline__ void fma4(float4& a, float s, const float4& b) {
    a.x = fmaf(s, b.x, a.x);
    a.y = fmaf(s, b.y, a.y);
    a.z = fmaf(s, b.z, a.z);
    a.w = fmaf(s, b.w, a.w);
}

// ---------------- CSR build (R13 structure) ----------------
__global__ void k_count(const int* __restrict__ ei, int E) {
    gdc_wait();
    int e = blockIdx.x * blockDim.x + threadIdx.x;
    if (e < E) atomicAdd(&g_deg[ei[E + e]], 1);
}

__global__ void k_scan1(int N) {
    __shared__ int sm[512];
    gdc_wait();
    int i = blockIdx.x * 512 + threadIdx.x;
    int v = (i < N) ? (g_deg[i] + 1) : 0;       // +1 self loop
    sm[threadIdx.x] = v;
    __syncthreads();
    #pragma unroll
    for (int off = 1; off < 512; off <<= 1) {
        int t = (threadIdx.x >= off) ? sm[threadIdx.x - off] : 0;
        __syncthreads();
        sm[threadIdx.x] += t;
        __syncthreads();
    }
    if (i < N) g_cursor[i] = sm[threadIdx.x];
    if (threadIdx.x == 511) g_bsum[blockIdx.x] = sm[511];
}

__global__ void k_scan23(int N, int nb) {
    __shared__ int pre;
    gdc_wait();
    if (threadIdx.x == 0) {
        int run = 0;
        for (int b = 0; b < (int)blockIdx.x; b++) run += g_bsum[b];
        pre = run;
    }
    __syncthreads();
    int i = blockIdx.x * 512 + threadIdx.x;
    if (i < N) {
        int incl = g_cursor[i] + pre;
        int deg  = g_deg[i] + 1;
        int excl = incl - deg;
        g_rowptr[i] = excl;
        g_cursor[i] = excl;
        g_deg[i] = 0;
        if (i == N - 1) g_rowptr[N] = incl;
    }
}

__global__ void k_scatter(const int* __restrict__ ei, int E, int N) {
    gdc_wait();
    int e = blockIdx.x * blockDim.x + threadIdx.x;
    if (e >= E + N) return;
    int s, d;
    if (e < E) { s = ei[e]; d = ei[E + e]; }
    else       { s = e - E; d = s; }
    int pos = atomicAdd(&g_cursor[d], 1);
    g_col[pos] = s;
}

__global__ void k_sort(int N) {
    gdc_wait();
    int warp = (blockIdx.x * blockDim.x + threadIdx.x) >> 5;
    int lane = threadIdx.x & 31;
    if (warp >= N) return;
    int beg = g_rowptr[warp];
    int cnt = g_rowptr[warp + 1] - beg;
    if (cnt <= 1) return;
    if (cnt <= 32) {
        int v = (lane < cnt) ? g_col[beg + lane] : 0x7fffffff;
        #pragma unroll
        for (int k = 2; k <= 32; k <<= 1) {
            #pragma unroll
            for (int jj = k >> 1; jj > 0; jj >>= 1) {
                int p = __shfl_xor_sync(FULLMASK, v, jj);
                bool up = ((lane & k) == 0);
                bool keepmin = (((lane & jj) == 0) == up);
                v = keepmin ? min(v, p) : max(v, p);
            }
        }
        if (lane < cnt) g_col[beg + lane] = v;
    } else if (lane == 0) {
        for (int a = 1; a < cnt; a++) {
            int key = g_col[beg + a], b = a - 1;
            while (b >= 0 && g_col[beg + b] > key) { g_col[beg + b + 1] = g_col[beg + b]; b--; }
            g_col[beg + b + 1] = key;
        }
    }
}

// ---------------- per-layer GEMM: coalesced smem staging + packed FFMA2 ----------------
__global__ void __launch_bounds__(128) k_gemm(
    const float* __restrict__ Wl, const float* __restrict__ al, const float* __restrict__ ar,
    int N)
{
    __shared__ float4 W4[HDIM * 8];
    __shared__ float4 al4[8], ar4[8];
    __shared__ float hbuf[128 * TS];          // 18 KB staging (rows padded to 36)
    int tid = threadIdx.x;
    // independent preamble: weights (harness inputs) — overlaps producer tail
    for (int q = tid; q < HDIM * 8; q += 128) W4[q] = reinterpret_cast<const float4*>(Wl)[q];
    if (tid < 8) { al4[tid] = reinterpret_cast<const float4*>(al)[tid];
                   ar4[tid] = reinterpret_cast<const float4*>(ar)[tid]; }
    gdc_wait();   // g_h produced by k_edge

    int nb = blockIdx.x * 128;
    int vrows = min(128, N - nb);
    int limit4 = vrows * 8;

    const float4* src = reinterpret_cast<const float4*>(g_h + (size_t)nb * HDIM);
    #pragma unroll
    for (int u = 0; u < 8; u++) {
        int q = tid + u * 128;
        if (q < limit4)
            *reinterpret_cast<float4*>(hbuf + (q >> 3) * TS + (q & 7) * 4) = src[q];
    }
    __syncthreads();

    int n = nb + tid;
    bool valid = n < N;
    unsigned long long acc2[16];
    if (valid) {
        float hs[32];
        #pragma unroll
        for (int u = 0; u < 8; u++) {
            float4 v = *reinterpret_cast<const float4*>(hbuf + tid * TS + 4 * u);
            hs[4*u] = v.x; hs[4*u+1] = v.y; hs[4*u+2] = v.z; hs[4*u+3] = v.w;
        }
        #pragma unroll
        for (int m = 0; m < 16; m++) acc2[m] = 0ull;
        #pragma unroll
        for (int k = 0; k < 32; k++) {
            unsigned long long ok2 = pack2(hs[k]);
            const ulonglong2* wp = reinterpret_cast<const ulonglong2*>(&W4[k * 8]);
            #pragma unroll
            for (int m = 0; m < 8; m++) {
                ulonglong2 w2 = wp[m];
                fma2(acc2[2*m],     ok2, w2.x);
                fma2(acc2[2*m + 1], ok2, w2.y);
            }
        }
    }
    __syncthreads();

    if (valid) {
        #pragma unroll
        for (int m = 0; m < 16; m++) {
            float2 f = unpack2(acc2[m]);
            hbuf[tid * TS + 2*m]     = f.x;
            hbuf[tid * TS + 2*m + 1] = f.y;
        }
    }
    __syncthreads();

    float4* dst = reinterpret_cast<float4*>(g_hp + (size_t)nb * HDIM);
    #pragma unroll
    for (int u = 0; u < 8; u++) {
        int q = tid + u * 128;
        if (q < limit4)
            dst[q] = *reinterpret_cast<const float4*>(hbuf + (q >> 3) * TS + (q & 7) * 4);
    }

    if (valid) {
        float t1 = 0.f, t2 = 0.f;
        #pragma unroll
        for (int j = 0; j < 8; j++) {
            float4 c = *reinterpret_cast<const float4*>(hbuf + tid * TS + 4 * j);
            float4 a4 = al4[j], r4 = ar4[j];
            t1 = fmaf(c.x, a4.x, t1); t1 = fmaf(c.y, a4.y, t1);
            t1 = fmaf(c.z, a4.z, t1); t1 = fmaf(c.w, a4.w, t1);
            t2 = fmaf(c.x, r4.x, t2); t2 = fmaf(c.y, r4.y, t2);
            t2 = fmaf(c.z, r4.z, t2); t2 = fmaf(c.w, r4.w, t2);
        }
        g_pl[n] = t1; g_pr[n] = t2;
    }
}

__global__ void __launch_bounds__(128) k_gemm_first(
    const float* __restrict__ x, const float* __restrict__ W0, const float* __restrict__ b0,
    const float* __restrict__ Ws0, const float* __restrict__ al, const float* __restrict__ ar,
    int N)
{
    __shared__ float4 W04[128 * 8];
    __shared__ float4 W4[HDIM * 8];
    __shared__ float4 b04[8], al4[8], ar4[8];
    int tid = threadIdx.x;
    for (int q = tid; q < 128 * 8; q += 128) W04[q] = reinterpret_cast<const float4*>(W0)[q];
    for (int q = tid; q < HDIM * 8; q += 128) W4[q] = reinterpret_cast<const float4*>(Ws0)[q];
    if (tid < 8) { b04[tid] = reinterpret_cast<const float4*>(b0)[tid];
                   al4[tid] = reinterpret_cast<const float4*>(al)[tid];
                   ar4[tid] = reinterpret_cast<const float4*>(ar)[tid]; }
    gdc_wait();   // ordering only (reads nothing produced; keeps completion chain transitive)
    __syncthreads();

    int n = blockIdx.x * 128 + tid;
    if (n >= N) return;

    float4 h4[8];
    #pragma unroll
    for (int j = 0; j < 8; j++) h4[j] = b04[j];
    #pragma unroll 4
    for (int k4 = 0; k4 < 32; k4++) {
        float4 xv = reinterpret_cast<const float4*>(x + n * 128)[k4];
        #pragma unroll
        for (int j = 0; j < 8; j++) {
            fma4(h4[j], xv.x, W04[(4*k4+0) * 8 + j]);
            fma4(h4[j], xv.y, W04[(4*k4+1) * 8 + j]);
            fma4(h4[j], xv.z, W04[(4*k4+2) * 8 + j]);
            fma4(h4[j], xv.w, W04[(4*k4+3) * 8 + j]);
        }
    }
    float hs[32];
    #pragma unroll
    for (int u = 0; u < 8; u++) {
        hs[4*u] = h4[u].x; hs[4*u+1] = h4[u].y; hs[4*u+2] = h4[u].z; hs[4*u+3] = h4[u].w;
    }
    float4 acc[8];
    #pragma unroll
    for (int j = 0; j < 8; j++) acc[j] = make_float4(0.f, 0.f, 0.f, 0.f);
    #pragma unroll
    for (int k = 0; k < 32; k++) {
        float ok = hs[k];
        #pragma unroll
        for (int j = 0; j < 8; j++) fma4(acc[j], ok, W4[k * 8 + j]);
    }
    float t1 = 0.f, t2 = 0.f;
    #pragma unroll
    for (int j = 0; j < 8; j++) {
        float4 a4 = al4[j], r4 = ar4[j], c = acc[j];
        t1 = fmaf(c.x, a4.x, t1); t1 = fmaf(c.y, a4.y, t1);
        t1 = fmaf(c.z, a4.z, t1); t1 = fmaf(c.w, a4.w, t1);
        t2 = fmaf(c.x, r4.x, t2); t2 = fmaf(c.y, r4.y, t2);
        t2 = fmaf(c.z, r4.z, t2); t2 = fmaf(c.w, r4.w, t2);
        reinterpret_cast<float4*>(g_hp + n * HDIM)[j] = c;
    }
    g_pl[n] = t1; g_pr[n] = t2;
}

__global__ void __launch_bounds__(128) k_gemm_last(
    const float* __restrict__ W16, const float* __restrict__ b16,
    float* __restrict__ out, int N)
{
    __shared__ float4 W4[HDIM * 4];
    __shared__ float4 b4[4];
    int tid = threadIdx.x;
    for (int q = tid; q < HDIM * 4; q += 128) W4[q] = reinterpret_cast<const float4*>(W16)[q];
    if (tid < 4) b4[tid] = reinterpret_cast<const float4*>(b16)[tid];
    gdc_wait();   // g_h produced by final k_edge
    __syncthreads();

    int n = blockIdx.x * 128 + tid;
    if (n >= N) return;

    float hs[32];
    #pragma unroll
    for (int u = 0; u < 8; u++) {
        float4 v = reinterpret_cast<const float4*>(g_h + n * HDIM)[u];
        hs[4*u] = v.x; hs[4*u+1] = v.y; hs[4*u+2] = v.z; hs[4*u+3] = v.w;
    }
    float4 acc[4];
    #pragma unroll
    for (int j = 0; j < 4; j++) acc[j] = b4[j];
    #pragma unroll
    for (int k = 0; k < 32; k++) {
        float ok = hs[k];
        #pragma unroll
        for (int j = 0; j < 4; j++) fma4(acc[j], ok, W4[k * 4 + j]);
    }
    #pragma unroll
    for (int j = 0; j < 4; j++) reinterpret_cast<float4*>(out + n * 16)[j] = acc[j];
}

// ---------------- edge layer (R15 verbatim: no-max softmax, guarded passes) ----------------
__global__ void __launch_bounds__(256) k_edge(
    const float* __restrict__ bcur, int N)
{
    __shared__ float tile[8][32 * TS];      // 36864 B
    __shared__ float bsm[HDIM];

    int tid = threadIdx.x;
    if (tid < HDIM) bsm[tid] = bcur[tid];   // independent preamble (input weights)
    gdc_wait();                             // g_hp/g_pl/g_pr produced by k_gemm*
    __syncthreads();

    const float* __restrict__ hp_in = g_hp;
    const float* __restrict__ pl_in = g_pl;
    const float* __restrict__ pr_in = g_pr;

    int lane = tid & 31;
    int g = lane >> 3;
    int j = lane & 7;
    int perm = 4 * j + g;
    int gb = lane & 24;

    int w = tid >> 5;
    float* tw = tile[w];
    unsigned tb = (unsigned)__cvta_generic_to_shared(tw) + (unsigned)(g * TS * 4 + j * 16);
    const char* hpb = reinterpret_cast<const char*>(hp_in);

    int wg = (blockIdx.x * blockDim.x + tid) >> 5;
    int nw = (gridDim.x * blockDim.x) >> 5;

    for (int i = wg; i < N; i += nw) {
        float4 hi4 = *reinterpret_cast<const float4*>(hp_in + i * HDIM + 4 * j);
        float pri = pr_in[i];
        int beg = g_rowptr[i], end = g_rowptr[i + 1];

        float den = 0.0f;
        float4 acc = make_float4(0.f, 0.f, 0.f, 0.f);

        for (int c = beg; c < end; c += 32) {
            int cnt = min(32, end - c);
            bool vld = perm < cnt;
            int s = g_col[c + min(perm, cnt - 1)];
            float pls = vld ? pl_in[s] : 0.0f;

            __syncwarp();
            #pragma unroll
            for (int t = 0; t < 8; t++) {
                if (4 * t < cnt) {
                    int se = __shfl_sync(FULLMASK, s, gb + t);
                    cp16(tb + (unsigned)(t * (4 * TS * 4)),
                         hpb + ((long long)se * 128 + j * 16));
                }
            }
            cp_commit();
            cp_wait0();
            __syncwarp();

            float dotv = 0.0f;
            #pragma unroll
            for (int t = 0; t < 8; t++) {
                if (4 * t < cnt) {
                    const float4 hj = *reinterpret_cast<const float4*>(tw + (4 * t + g) * TS + 4 * j);
                    float d = hj.x * hi4.x;
                    d = fmaf(hj.y, hi4.y, d);
                    d = fmaf(hj.z, hi4.z, d);
                    d = fmaf(hj.w, hi4.w, d);
                    d += __shfl_xor_sync(FULLMASK, d, 4);
                    d += __shfl_xor_sync(FULLMASK, d, 2);
                    d += __shfl_xor_sync(FULLMASK, d, 1);
                    if (j == t) dotv = d;
                }
            }

            float e1  = fexp(-fabsf(dotv));
            float r   = rcp1p(e1);
            float sig = (dotv >= 0.0f) ? r : 1.0f - r;
            float a   = (pls + pri) * sig;
            a = (a >= 0.0f) ? a : 0.2f * a;
            a = fminf(a, 80.0f);                       // overflow guard

            float wv = vld ? fexp(a) : 0.0f;           // exact 0 for padding lanes
            float ws = wv;
            #pragma unroll
            for (int off = 16; off; off >>= 1) ws += __shfl_xor_sync(FULLMASK, ws, off);
            den += ws;

            #pragma unroll
            for (int t = 0; t < 8; t++) {
                if (4 * t < cnt) {
                    float we = __shfl_sync(FULLMASK, wv, gb + t);
                    const float4 hj = *reinterpret_cast<const float4*>(tw + (4 * t + g) * TS + 4 * j);
                    acc.x = fmaf(we, hj.x, acc.x);
                    acc.y = fmaf(we, hj.y, acc.y);
                    acc.z = fmaf(we, hj.z, acc.z);
                    acc.w = fmaf(we, hj.w, acc.w);
                }
            }
        }

        #pragma unroll
        for (int off = 8; off <= 16; off <<= 1) {
            acc.x += __shfl_xor_sync(FULLMASK, acc.x, off);
            acc.y += __shfl_xor_sync(FULLMASK, acc.y, off);
            acc.z += __shfl_xor_sync(FULLMASK, acc.z, off);
            acc.w += __shfl_xor_sync(FULLMASK, acc.w, off);
        }
        if (g == 0) {
            float rden = __fdividef(1.0f, den);
            float4 b4 = *reinterpret_cast<const float4*>(bsm + 4 * j);
            float4 o4;
            o4.x = fmaxf(fmaf(acc.x, rden, b4.x), 0.0f);
            o4.y = fmaxf(fmaf(acc.y, rden, b4.y), 0.0f);
            o4.z = fmaxf(fmaf(acc.z, rden, b4.z), 0.0f);
            o4.w = fmaxf(fmaf(acc.w, rden, b4.w), 0.0f);
            *reinterpret_cast<float4*>(g_h + i * HDIM + 4 * j) = o4;
        }
    }
}

// ---------------- host: PDL launches (programmatic stream serialization) ----------------
template <typename... Args>
static void launch_pdl(void (*kern)(Args...), dim3 grid, dim3 block, Args... args) {
    cudaLaunchConfig_t cfg = {};
    cfg.gridDim = grid;
    cfg.blockDim = block;
    cfg.dynamicSmemBytes = 0;
    cfg.stream = 0;
    cudaLaunchAttribute attr[1];
    attr[0].id = cudaLaunchAttributeProgrammaticStreamSerialization;
    attr[0].val.programmaticStreamSerializationAllowed = 1;
    cfg.attrs = attr;
    cfg.numAttrs = 1;
    cudaLaunchKernelEx(&cfg, kern, args...);
}

extern "C" void kernel_launch(void* const* d_in, const int* in_sizes, int n_in,
                              void* d_out, int out_size) {
    const float* x   = (const float*)d_in[0];
    const int*   ei  = (const int*)d_in[1];
    const float* W0  = (const float*)d_in[2];
    const float* b0  = (const float*)d_in[3];
    const float* Ws  = (const float*)d_in[4];
    const float* al  = (const float*)d_in[5];
    const float* ar  = (const float*)d_in[6];
    const float* bs  = (const float*)d_in[7];
    const float* W16 = (const float*)d_in[8];
    const float* b16 = (const float*)d_in[9];
    float* out = (float*)d_out;

    const int N = in_sizes[0] / 128;
    const int E = in_sizes[1] / 2;
    const int L = 15;
    const int nb = (N + 511) / 512;
    const int gN = (N + 127) / 128;

    // ---- CSR build ----
    launch_pdl(k_count, dim3((E + 255) / 256), dim3(256), ei, E);
    launch_pdl(k_scan1, dim3(nb), dim3(512), N);
    launch_pdl(k_scan23, dim3(nb), dim3(512), N, nb);
    launch_pdl(k_scatter, dim3((E + N + 255) / 256), dim3(256), ei, E, N);
    launch_pdl(k_sort, dim3((N * 32 + 255) / 256), dim3(256), N);

    // ---- input transform ----
    launch_pdl(k_gemm_first, dim3(gN), dim3(128), x, W0, b0, Ws, al, ar, N);

    // ---- 15 SuperGAT layers ----
    for (int l = 0; l < L; l++) {
        launch_pdl(k_edge, dim3(740), dim3(256), (const float*)(bs + l * 32), N);
        if (l < L - 1)
            launch_pdl(k_gemm, dim3(gN), dim3(128),
                       (const float*)(Ws + (l + 1) * 32 * 32),
                       (const float*)(al + (l + 1) * 32),
                       (const float*)(ar + (l + 1) * 32), N);
        else
            launch_pdl(k_gemm_last, dim3(gN), dim3(128), W16, b16, out, N);
    }
}